// round 1
// baseline (speedup 1.0000x reference)
#include <cuda_runtime.h>

#define BB    4
#define NQ    2048
#define DIM   1024
#define HEADS 16
#define DH    64
#define INNER 1024
#define NCOLS 3072

#define A_ELEMS (BB*NQ*INNER)        // 8388608
#define M_ELEMS (BB*HEADS*DH*DH)     // 262144
#define Z_ELEMS (BB*HEADS*DH)        // 4096

// scratch: q,k,v in [b,h,n,d] layout
__device__ float g_q[BB*HEADS*NQ*DH];
__device__ float g_k[BB*HEADS*NQ*DH];
__device__ float g_v[BB*HEADS*NQ*DH];

// ---------------------------------------------------------------------------
// Kernel 1: qkv = x @ W_qkv, scattered into g_q/g_k/g_v [b,h,n,d]
// C[8192,3072] = x[8192,1024] @ W[1024,3072]
// 64x64 tile, BK=16, 256 threads, 4x4 per thread.
// ---------------------------------------------------------------------------
__global__ __launch_bounds__(256)
void qkv_gemm_kernel(const float* __restrict__ x, const float* __restrict__ W) {
    __shared__ float As[16][64];   // As[k][m]
    __shared__ float Bs[16][64];   // Bs[k][n]
    const int tid = threadIdx.x;
    const int bm = blockIdx.y * 64;
    const int bn = blockIdx.x * 64;
    const int tx = tid & 15, ty = tid >> 4;

    const int a_m = tid >> 2;            // 0..63
    const int a_k = (tid & 3) << 2;      // 0,4,8,12
    const int b_k = tid >> 4;            // 0..15
    const int b_n = (tid & 15) << 2;     // 0..60

    float c[4][4] = {};
    const float* xp = x + (size_t)(bm + a_m) * DIM + a_k;
    const float* wp = W + (size_t)b_k * NCOLS + bn + b_n;

    for (int k0 = 0; k0 < DIM; k0 += 16) {
        float4 av = *(const float4*)(xp + k0);
        float4 bv = *(const float4*)(wp + (size_t)k0 * NCOLS);
        __syncthreads();
        As[a_k+0][a_m] = av.x;
        As[a_k+1][a_m] = av.y;
        As[a_k+2][a_m] = av.z;
        As[a_k+3][a_m] = av.w;
        *(float4*)&Bs[b_k][b_n] = bv;
        __syncthreads();
        #pragma unroll
        for (int kk = 0; kk < 16; kk++) {
            float4 a4 = *(const float4*)&As[kk][ty << 2];
            float4 b4 = *(const float4*)&Bs[kk][tx << 2];
            c[0][0] += a4.x*b4.x; c[0][1] += a4.x*b4.y; c[0][2] += a4.x*b4.z; c[0][3] += a4.x*b4.w;
            c[1][0] += a4.y*b4.x; c[1][1] += a4.y*b4.y; c[1][2] += a4.y*b4.z; c[1][3] += a4.y*b4.w;
            c[2][0] += a4.z*b4.x; c[2][1] += a4.z*b4.y; c[2][2] += a4.z*b4.z; c[2][3] += a4.z*b4.w;
            c[3][0] += a4.w*b4.x; c[3][1] += a4.w*b4.y; c[3][2] += a4.w*b4.z; c[3][3] += a4.w*b4.w;
        }
    }

    // epilogue scatter: bn multiple of 64, so part/head constant per CTA
    const int part = bn >> 10;                 // 0=q,1=k,2=v
    const int h    = (bn & 1023) >> 6;
    float* dst = (part == 0) ? g_q : (part == 1) ? g_k : g_v;
    #pragma unroll
    for (int i = 0; i < 4; i++) {
        int r  = bm + (ty << 2) + i;
        int b  = r >> 11;
        int n  = r & 2047;
        float4 v4 = make_float4(c[i][0], c[i][1], c[i][2], c[i][3]);
        size_t off = (((size_t)(b*HEADS + h) * NQ + n) * DH) + (tx << 2);
        *(float4*)&dst[off] = v4;
    }
}

// ---------------------------------------------------------------------------
// Kernel 2: flash attention + compressive-memory branch + gate -> A
// grid (16 qtiles, 16 heads, 4 batch), 128 threads, 1 thread = 1 query row.
// ---------------------------------------------------------------------------
__global__ __launch_bounds__(128, 2)
void attn_kernel(const float* __restrict__ M_in, const float* __restrict__ Z_in,
                 const float* __restrict__ beta_gate, float* __restrict__ outA) {
    __shared__ float Mt[DH][DH];   // Mt[v][d] = M[d][v]
    __shared__ float Zs[DH];
    __shared__ float Ks[32][DH];
    __shared__ float Vs[32][DH];

    const int tid = threadIdx.x;
    const int b = blockIdx.z, h = blockIdx.y;
    const int row = blockIdx.x * 128 + tid;
    const int bh = b * HEADS + h;

    const float* Mg = M_in + (size_t)bh * DH * DH;
    for (int e = tid; e < DH*DH; e += 128) {
        int d = e >> 6, v = e & 63;
        Mt[v][d] = Mg[e];
    }
    if (tid < DH) Zs[tid] = Z_in[bh*DH + tid];

    float q[DH];
    {
        const float4* qp = (const float4*)(g_q + ((size_t)bh*NQ + row)*DH);
        #pragma unroll
        for (int i = 0; i < 16; i++) {
            float4 t = qp[i];
            q[4*i] = t.x; q[4*i+1] = t.y; q[4*i+2] = t.z; q[4*i+3] = t.w;
        }
    }

    float o[DH];
    #pragma unroll
    for (int d = 0; d < DH; d++) o[d] = 0.f;
    float mrow = -1e30f, l = 0.f;

    const float* kg = g_k + (size_t)bh*NQ*DH;
    const float* vg = g_v + (size_t)bh*NQ*DH;

    for (int jt = 0; jt < NQ; jt += 32) {
        __syncthreads();
        #pragma unroll
        for (int i = 0; i < 4; i++) {
            int fidx = tid + 128*i;          // 0..511
            int j = fidx >> 4, dd = (fidx & 15) << 2;
            *(float4*)&Ks[j][dd] = *(const float4*)&kg[(size_t)(jt+j)*DH + dd];
            *(float4*)&Vs[j][dd] = *(const float4*)&vg[(size_t)(jt+j)*DH + dd];
        }
        __syncthreads();

        float s[32];
        float tmax = -1e30f;
        #pragma unroll
        for (int j = 0; j < 32; j++) {
            float acc = 0.f;
            const float4* k4 = (const float4*)Ks[j];
            #pragma unroll
            for (int dd = 0; dd < 16; dd++) {
                float4 kk4 = k4[dd];
                acc += q[4*dd]*kk4.x + q[4*dd+1]*kk4.y + q[4*dd+2]*kk4.z + q[4*dd+3]*kk4.w;
            }
            s[j] = acc * 0.125f;
            tmax = fmaxf(tmax, s[j]);
        }
        float mnew = fmaxf(mrow, tmax);
        float corr = __expf(mrow - mnew);
        l *= corr;
        #pragma unroll
        for (int d = 0; d < DH; d++) o[d] *= corr;
        #pragma unroll
        for (int j = 0; j < 32; j++) {
            float p = __expf(s[j] - mnew);
            l += p;
            const float4* v4 = (const float4*)Vs[j];
            #pragma unroll
            for (int dd = 0; dd < 16; dd++) {
                float4 vv = v4[dd];
                o[4*dd]   += p*vv.x;
                o[4*dd+1] += p*vv.y;
                o[4*dd+2] += p*vv.z;
                o[4*dd+3] += p*vv.w;
            }
        }
        mrow = mnew;
    }

    // memory branch: sigma(q) = q>0 ? q+1 : exp(q)
    float sq[DH];
    #pragma unroll
    for (int d = 0; d < DH; d++) sq[d] = (q[d] > 0.f) ? (q[d] + 1.f) : __expf(q[d]);
    float den = 0.f;
    #pragma unroll
    for (int d = 0; d < DH; d++) den += sq[d]*Zs[d];

    float gv = 1.f / (1.f + __expf(-beta_gate[h]));
    float inv_l = 1.f / l;
    float inv_den = 1.f / den;

    float* op = outA + ((size_t)(b*NQ + row)) * INNER + h*DH;
    #pragma unroll
    for (int v0 = 0; v0 < DH; v0 += 4) {
        float n0 = 0.f, n1 = 0.f, n2 = 0.f, n3 = 0.f;
        const float4* m0 = (const float4*)Mt[v0+0];
        const float4* m1 = (const float4*)Mt[v0+1];
        const float4* m2 = (const float4*)Mt[v0+2];
        const float4* m3 = (const float4*)Mt[v0+3];
        #pragma unroll
        for (int dd = 0; dd < 16; dd++) {
            float4 a = m0[dd], bq = m1[dd], cq = m2[dd], dq = m3[dd];
            n0 += sq[4*dd]*a.x  + sq[4*dd+1]*a.y  + sq[4*dd+2]*a.z  + sq[4*dd+3]*a.w;
            n1 += sq[4*dd]*bq.x + sq[4*dd+1]*bq.y + sq[4*dd+2]*bq.z + sq[4*dd+3]*bq.w;
            n2 += sq[4*dd]*cq.x + sq[4*dd+1]*cq.y + sq[4*dd+2]*cq.z + sq[4*dd+3]*cq.w;
            n3 += sq[4*dd]*dq.x + sq[4*dd+1]*dq.y + sq[4*dd+2]*dq.z + sq[4*dd+3]*dq.w;
        }
        float4 r;
        r.x = gv*(n0*inv_den) + (1.f-gv)*(o[v0+0]*inv_l);
        r.y = gv*(n1*inv_den) + (1.f-gv)*(o[v0+1]*inv_l);
        r.z = gv*(n2*inv_den) + (1.f-gv)*(o[v0+2]*inv_l);
        r.w = gv*(n3*inv_den) + (1.f-gv)*(o[v0+3]*inv_l);
        *(float4*)&op[v0] = r;
    }
}

// ---------------------------------------------------------------------------
// Kernel 3: state update. One CTA per (b,h), 256 threads, chunks of 32 rows.
// M_new = beta*M + sk^T @ (v - moment),  Z_new = beta*Z + sum_n sk
// ---------------------------------------------------------------------------
#define CN 32
__global__ __launch_bounds__(256)
void state_kernel(const float* __restrict__ M_in, const float* __restrict__ Z_in,
                  const float* __restrict__ beta_lin, float* __restrict__ out) {
    __shared__ float Ms[DH][DH];       // Ms[d][v]
    __shared__ float Zs[DH];
    __shared__ float sks[CN][DH];
    __shared__ float dvs[CN][DH];
    __shared__ float invden[CN];

    const int tid = threadIdx.x;
    const int bh = blockIdx.x;

    const float* Mg = M_in + (size_t)bh * DH * DH;
    for (int e = tid; e < DH*DH; e += 256) Ms[e >> 6][e & 63] = Mg[e];
    if (tid < DH) Zs[tid] = Z_in[bh*DH + tid];

    const float* kg = g_k + (size_t)bh*NQ*DH;
    const float* vg = g_v + (size_t)bh*NQ*DH;

    const int dgrp = tid >> 2;          // 0..63 : d row owned
    const int vb   = (tid & 3) << 4;    // v block start
    float macc[16];
    #pragma unroll
    for (int i = 0; i < 16; i++) macc[i] = 0.f;
    float zacc = 0.f;

    for (int n0 = 0; n0 < NQ; n0 += CN) {
        __syncthreads();
        #pragma unroll
        for (int i = 0; i < 2; i++) {
            int fidx = tid + 256*i;       // 0..511
            int n = fidx >> 4, dd = (fidx & 15) << 2;
            float4 kv = *(const float4*)&kg[(size_t)(n0+n)*DH + dd];
            kv.x = (kv.x > 0.f) ? (kv.x + 1.f) : __expf(kv.x);
            kv.y = (kv.y > 0.f) ? (kv.y + 1.f) : __expf(kv.y);
            kv.z = (kv.z > 0.f) ? (kv.z + 1.f) : __expf(kv.z);
            kv.w = (kv.w > 0.f) ? (kv.w + 1.f) : __expf(kv.w);
            *(float4*)&sks[n][dd] = kv;
            *(float4*)&dvs[n][dd] = *(const float4*)&vg[(size_t)(n0+n)*DH + dd];
        }
        __syncthreads();
        if (tid < CN) {
            float acc = 0.f;
            #pragma unroll
            for (int d = 0; d < DH; d++) acc += sks[tid][d]*Zs[d];
            invden[tid] = 1.f / acc;
        }
        __syncthreads();
        // moment & diff: CN*DH = 2048 entries / 256 threads = 8 each
        #pragma unroll
        for (int e = 0; e < 8; e++) {
            int idx = tid + 256*e;
            int n = idx >> 6, v = idx & 63;
            float acc = 0.f;
            #pragma unroll
            for (int d = 0; d < DH; d++) acc += sks[n][d]*Ms[d][v];
            dvs[n][v] -= acc * invden[n];
        }
        __syncthreads();
        // accumulate outer product
        #pragma unroll 4
        for (int n = 0; n < CN; n++) {
            float skdn = sks[n][dgrp];
            const float* dv = &dvs[n][vb];
            #pragma unroll
            for (int vv = 0; vv < 16; vv++) macc[vv] += skdn * dv[vv];
        }
        if (tid < DH) {
            #pragma unroll
            for (int n = 0; n < CN; n++) zacc += sks[n][tid];
        }
    }
    __syncthreads();

    float beta = 1.f / (1.f + __expf(-beta_lin[0]));
    beta = fminf(fmaxf(beta, 0.9f), 0.999f);

    float* mout = out + A_ELEMS + (size_t)bh * DH * DH;
    #pragma unroll
    for (int vv = 0; vv < 16; vv++)
        mout[dgrp*DH + vb + vv] = beta*Ms[dgrp][vb+vv] + macc[vv];
    if (tid < DH)
        out[A_ELEMS + M_ELEMS + bh*DH + tid] = beta*Zs[tid] + zacc;
}

// ---------------------------------------------------------------------------
extern "C" void kernel_launch(void* const* d_in, const int* in_sizes, int n_in,
                              void* d_out, int out_size) {
    const float* x         = (const float*)d_in[0];
    const float* M         = (const float*)d_in[1];
    const float* Z         = (const float*)d_in[2];
    const float* W         = (const float*)d_in[3];
    const float* beta_lin  = (const float*)d_in[4];
    const float* beta_gate = (const float*)d_in[5];
    float* out = (float*)d_out;

    qkv_gemm_kernel<<<dim3(NCOLS/64, (BB*NQ)/64), 256>>>(x, W);
    attn_kernel<<<dim3(NQ/128, HEADS, BB), 128>>>(M, Z, beta_gate, out);
    state_kernel<<<BB*HEADS, 256>>>(M, Z, beta_lin, out);
}